// round 5
// baseline (speedup 1.0000x reference)
#include <cuda_runtime.h>
#include <cstdint>

#define HD 128
#define WD 128
#define OC 128
#define CIN 64
#define XST 136                 // padded row stride (floats): 136 % 32 == 8 -> conflict-free frags
#define WBYTES (64 * XST * 4)   // one tap tile: 64 k-rows x 136 floats = 34816 B

// smem byte offsets
#define SM_XS   0               // 4 * 64 * 136 * 4 = 139264
#define SM_W    139264          // 2 * 34816 = 69632
#define SM_CS   208896          // 4 * 136 * 4 = 2176
#define SM_PS   211072          // 2 * 128 * 4 = 1024
#define SM_BIAS 212096          // 512
#define SM_MB   212608          // 2 mbarriers
#define SM_TOT  212640

__device__ __align__(128) float g_Wt[9 * 64 * XST];   // [tap][ci][o(pad 136)] tf32-rounded

// ---------- helpers ----------
__device__ __forceinline__ uint32_t smem_u32(const void* p) {
    uint32_t a;
    asm("{ .reg .u64 t; cvta.to.shared.u64 t, %1; cvt.u32.u64 %0, t; }" : "=r"(a) : "l"(p));
    return a;
}
__device__ __forceinline__ float tf32r(float v) {
    float r; asm("cvt.rna.tf32.f32 %0, %1;" : "=f"(r) : "f"(v)); return r;
}
#define MB_INIT(mb, c)   asm volatile("mbarrier.init.shared.b64 [%0], %1;" :: "r"(mb), "r"((uint32_t)(c)) : "memory")
#define MB_EXPECT(mb, n) asm volatile("mbarrier.arrive.expect_tx.shared.b64 _, [%0], %1;" :: "r"(mb), "r"((uint32_t)(n)) : "memory")
#define BULK_G2S(dst, src, n, mb) \
    asm volatile("cp.async.bulk.shared::cta.global.mbarrier::complete_tx::bytes [%0], [%1], %2, [%3];" \
                 :: "r"(dst), "l"(src), "r"((uint32_t)(n)), "r"(mb) : "memory")
#define MB_WAIT(mb, par) do {                                                          \
    uint32_t _m = (mb), _p = (par), _d;                                                \
    asm volatile("{\n\t.reg .pred p;\n\t"                                              \
        "mbarrier.try_wait.parity.acquire.cta.shared::cta.b64 p, [%1], %2;\n\t"        \
        "selp.b32 %0,1,0,p;\n\t}" : "=r"(_d) : "r"(_m), "r"(_p) : "memory");           \
    if (!_d) {                                                                         \
        asm volatile("{\n\t.reg .pred P1;\n\tWL_%=:\n\t"                               \
            "mbarrier.try_wait.parity.acquire.cta.shared::cta.b64 P1, [%0], %1, 0x989680;\n\t" \
            "@P1 bra.uni WDN_%=;\n\tbra.uni WL_%=;\n\tWDN_%=:\n\t}"                    \
            :: "r"(_m), "r"(_p) : "memory");                                           \
    }                                                                                  \
} while (0)

// m16n8k8 tf32 HMMA (sm_80+ baseline ISA)
#define MMA8(d, a, bq)                                                                 \
    asm volatile("mma.sync.aligned.m16n8k8.row.col.f32.tf32.tf32.f32 "                 \
        "{%0,%1,%2,%3}, {%4,%5,%6,%7}, {%8,%9}, {%0,%1,%2,%3};"                        \
        : "+f"((d)[0]), "+f"((d)[1]), "+f"((d)[2]), "+f"((d)[3])                       \
        : "r"(__float_as_uint((a)[0])), "r"(__float_as_uint((a)[1])),                  \
          "r"(__float_as_uint((a)[2])), "r"(__float_as_uint((a)[3])),                  \
          "r"(__float_as_uint((bq)[0])), "r"(__float_as_uint((bq)[1])))

// ---------- prepass: weights -> [tap][ci][o] padded, tf32-rounded ----------
__global__ void prep_w(const float* __restrict__ wt) {
    int i = blockIdx.x * blockDim.x + threadIdx.x;
    if (i >= 9 * 64 * XST) return;
    int tap = i / (64 * XST), r = i % (64 * XST);
    int ci = r / XST, o = r % XST;
    float v = 0.f;
    if (o < 128) v = tf32r(wt[o * 576 + ci * 9 + tap]);   // wt[o][ci][kh][kw], tap = kh*3+kw
    g_Wt[i] = v;
}

// ---------- main kernel: one CTA per (b, h-pair), 512 threads / 16 warps ----------
__global__ __launch_bounds__(512, 1)
void patchconv_mma(const float* __restrict__ x, const float* __restrict__ bias,
                   float* __restrict__ out) {
    extern __shared__ __align__(16) char smem[];
    float* sxs   = (float*)(smem + SM_XS);    // [r(4)][ci(64)][w(136)], w idx = xcol+4
    float* scs   = (float*)(smem + SM_CS);    // channel sums [r][w]
    float* sps   = (float*)(smem + SM_PS);    // 3x3 patch sums [hl][w]
    float* sbias = (float*)(smem + SM_BIAS);
    const uint32_t sb  = smem_u32(smem);
    const uint32_t mb0 = sb + SM_MB, mb1 = sb + SM_MB + 8;

    const int tid = threadIdx.x, lane = tid & 31, wid = tid >> 5;
    const int h0 = blockIdx.x * 2, b = blockIdx.y;

    if (tid == 0) { MB_INIT(mb0, 1); MB_INIT(mb1, 1); }
    if (tid < 128) sbias[tid] = bias[tid];
    __syncthreads();
    if (tid == 0) { MB_EXPECT(mb0, WBYTES); BULK_G2S(sb + SM_W, (const void*)g_Wt, WBYTES, mb0); }

    // ---- stage x: 4 halo rows, tf32-rounded, zero borders ----
    const float* xb = x + (size_t)b * CIN * HD * WD;
    for (int idx = wid; idx < 4 * 64; idx += 16) {
        int r = idx >> 6, ci = idx & 63;
        int hr = h0 - 1 + r;
        float4 v = make_float4(0.f, 0.f, 0.f, 0.f);
        if ((unsigned)hr < 128u)
            v = *(const float4*)(xb + ((size_t)ci * HD + hr) * WD + lane * 4);
        v.x = tf32r(v.x); v.y = tf32r(v.y); v.z = tf32r(v.z); v.w = tf32r(v.w);
        float* d = sxs + (r * 64 + ci) * XST;
        *(float4*)(d + 4 + lane * 4) = v;
        if (lane < 2) *(float4*)(d + lane * 132) = make_float4(0.f, 0.f, 0.f, 0.f);
    }
    __syncthreads();

    // ---- channel sums + 3x3 patch sums (rank-1 term), fp32 on rounded data ----
    for (int p = tid; p < 4 * XST; p += 512) {
        int r = p / XST, w = p - r * XST;
        float s = 0.f;
        const float* c = sxs + r * 64 * XST + w;
        #pragma unroll 8
        for (int k = 0; k < 64; k++) s += c[k * XST];
        scs[p] = s;
    }
    __syncthreads();
    if (tid < 256) {
        int hl = tid >> 7, wo = tid & 127;
        float s = 0.f;
        #pragma unroll
        for (int kh = 0; kh < 3; kh++)
            #pragma unroll
            for (int kw = 0; kw < 3; kw++)
                s += scs[(hl + kh) * XST + wo + kw + 3];
        sps[tid] = s;
    }

    // ---- main loop: 9 taps, double-buffered weights, warp tile 32M x 64N ----
    const int warp_m = wid >> 1, warp_n = wid & 1;   // warp_m 0..7, warp_n 0..1
    const int hl = warp_m >> 2;                       // h-row within pair
    const int wb = (warp_m & 3) * 32;                 // w base
    const int ob = warp_n * 64;                       // o base

    float acc[2][8][4];
    #pragma unroll
    for (int mi = 0; mi < 2; mi++)
        #pragma unroll
        for (int ni = 0; ni < 8; ni++)
            #pragma unroll
            for (int j = 0; j < 4; j++) acc[mi][ni][j] = 0.f;

    #pragma unroll 1
    for (int t = 0; t < 9; t++) {
        const int buf = t & 1;
        if (t < 8 && tid == 0) {
            int nb = buf ^ 1;
            uint32_t m = nb ? mb1 : mb0;
            MB_EXPECT(m, WBYTES);
            BULK_G2S(sb + SM_W + nb * WBYTES, (const void*)(g_Wt + (t + 1) * 64 * XST), WBYTES, m);
        }
        MB_WAIT(buf ? mb1 : mb0, (t >> 1) & 1);

        const int kh = t / 3, kw = t - kh * 3;
        const float* Ab = sxs + (hl + kh) * 64 * XST + (lane & 3) * XST + wb + kw + 3 + (lane >> 2);
        const float* Bb = (const float*)(smem + SM_W + buf * WBYTES) + (lane & 3) * XST + ob + (lane >> 2);

        #pragma unroll
        for (int s = 0; s < 8; s++) {
            const float* Ap = Ab + s * 8 * XST;
            const float* Bp = Bb + s * 8 * XST;
            float a[2][4], bq[8][2];
            #pragma unroll
            for (int mi = 0; mi < 2; mi++) {
                a[mi][0] = Ap[mi * 16];
                a[mi][1] = Ap[mi * 16 + 8];
                a[mi][2] = Ap[mi * 16 + 4 * XST];
                a[mi][3] = Ap[mi * 16 + 8 + 4 * XST];
            }
            #pragma unroll
            for (int ni = 0; ni < 8; ni++) {
                bq[ni][0] = Bp[ni * 8];
                bq[ni][1] = Bp[ni * 8 + 4 * XST];
            }
            #pragma unroll
            for (int mi = 0; mi < 2; mi++)
                #pragma unroll
                for (int ni = 0; ni < 8; ni++)
                    MMA8(acc[mi][ni], a[mi], bq[ni]);
        }
        __syncthreads();   // all warps done with buf before it is refilled at t+2
    }

    // ---- epilogue: + bias[o] + 0.1*(h+w)*patch_sum, 32B-sector-aligned stores ----
    const int hg = h0 + hl;
    float* outb = out + (size_t)b * OC * HD * WD + (size_t)hg * WD;
    #pragma unroll
    for (int mi = 0; mi < 2; mi++) {
        int w0r = wb + mi * 16 + (lane >> 2);
        float c0 = 0.1f * (float)(hg + w0r) * sps[hl * 128 + w0r];
        float c1 = 0.1f * (float)(hg + w0r + 8) * sps[hl * 128 + w0r + 8];
        #pragma unroll
        for (int ni = 0; ni < 8; ni++) {
            int o = ob + ni * 8 + (lane & 3) * 2;
            float bz0 = sbias[o], bz1 = sbias[o + 1];
            float* p0 = outb + (size_t)o * (HD * WD);
            float* p1 = p0 + HD * WD;
            p0[w0r]     = acc[mi][ni][0] + c0 + bz0;
            p1[w0r]     = acc[mi][ni][1] + c0 + bz1;
            p0[w0r + 8] = acc[mi][ni][2] + c1 + bz0;
            p1[w0r + 8] = acc[mi][ni][3] + c1 + bz1;
        }
    }
}

extern "C" void kernel_launch(void* const* d_in, const int* in_sizes, int n_in,
                              void* d_out, int out_size) {
    const float* x    = (const float*)d_in[0];
    const float* wt   = (const float*)d_in[1];
    const float* bias = (const float*)d_in[2];
    float* out        = (float*)d_out;
    cudaFuncSetAttribute(patchconv_mma, cudaFuncAttributeMaxDynamicSharedMemorySize, SM_TOT);
    prep_w<<<(9 * 64 * XST + 255) / 256, 256>>>(wt);
    patchconv_mma<<<dim3(64, 16), 512, SM_TOT>>>(x, bias, out);
}

// round 6
// speedup vs baseline: 1.1212x; 1.1212x over previous
#include <cuda_runtime.h>
#include <cstdint>

#define HD 128
#define WD 128
#define OC 128
#define CIN 64
#define XST 136                 // x smem row stride (floats): conflict-free frag reads
#define WBYTES 32768            // one tap of pre-arranged B fragments

// smem byte offsets
#define SM_XS   0               // 4 * 64 * 136 * 4 = 139264
#define SM_W    139264          // 2 * 32768 = 65536
#define SM_CS   204800          // 4 * 136 * 4 = 2176
#define SM_PS   206976          // 2 * 128 * 4 = 1024
#define SM_BIAS 208000          // 512
#define SM_MB   208512          // 2 mbarriers
#define SM_TOT  208544

// B fragments, register-image order: [tap][s(8)][g(16)][lane(32)][2]
__device__ __align__(128) float g_Wf[9 * 8 * 16 * 32 * 2];

// ---------- helpers ----------
__device__ __forceinline__ uint32_t smem_u32(const void* p) {
    uint32_t a;
    asm("{ .reg .u64 t; cvta.to.shared.u64 t, %1; cvt.u32.u64 %0, t; }" : "=r"(a) : "l"(p));
    return a;
}
__device__ __forceinline__ float tf32r(float v) {
    float r; asm("cvt.rna.tf32.f32 %0, %1;" : "=f"(r) : "f"(v)); return r;
}
#define MB_INIT(mb, c)   asm volatile("mbarrier.init.shared.b64 [%0], %1;" :: "r"(mb), "r"((uint32_t)(c)) : "memory")
#define MB_EXPECT(mb, n) asm volatile("mbarrier.arrive.expect_tx.shared.b64 _, [%0], %1;" :: "r"(mb), "r"((uint32_t)(n)) : "memory")
#define BULK_G2S(dst, src, n, mb) \
    asm volatile("cp.async.bulk.shared::cta.global.mbarrier::complete_tx::bytes [%0], [%1], %2, [%3];" \
                 :: "r"(dst), "l"(src), "r"((uint32_t)(n)), "r"(mb) : "memory")
#define MB_WAIT(mb, par) do {                                                          \
    uint32_t _m = (mb), _p = (par), _d;                                                \
    asm volatile("{\n\t.reg .pred p;\n\t"                                              \
        "mbarrier.try_wait.parity.acquire.cta.shared::cta.b64 p, [%1], %2;\n\t"        \
        "selp.b32 %0,1,0,p;\n\t}" : "=r"(_d) : "r"(_m), "r"(_p) : "memory");           \
    if (!_d) {                                                                         \
        asm volatile("{\n\t.reg .pred P1;\n\tWL_%=:\n\t"                               \
            "mbarrier.try_wait.parity.acquire.cta.shared::cta.b64 P1, [%0], %1, 0x989680;\n\t" \
            "@P1 bra.uni WDN_%=;\n\tbra.uni WL_%=;\n\tWDN_%=:\n\t}"                    \
            :: "r"(_m), "r"(_p) : "memory");                                           \
    }                                                                                  \
} while (0)

// m16n8k8 tf32 HMMA (sm_80+ baseline ISA)
#define MMA8(d, a, bq)                                                                 \
    asm volatile("mma.sync.aligned.m16n8k8.row.col.f32.tf32.tf32.f32 "                 \
        "{%0,%1,%2,%3}, {%4,%5,%6,%7}, {%8,%9}, {%0,%1,%2,%3};"                        \
        : "+f"((d)[0]), "+f"((d)[1]), "+f"((d)[2]), "+f"((d)[3])                       \
        : "r"(__float_as_uint((a)[0])), "r"(__float_as_uint((a)[1])),                  \
          "r"(__float_as_uint((a)[2])), "r"(__float_as_uint((a)[3])),                  \
          "r"(__float_as_uint((bq).x)), "r"(__float_as_uint((bq).y)))

// ---------- prepass: weights -> per-thread B fragment images ----------
__global__ void prep_w(const float* __restrict__ wt) {
    int i = blockIdx.x * blockDim.x + threadIdx.x;   // one float2 per thread
    if (i >= 9 * 8 * 16 * 32) return;
    int tap = i >> 12;
    int r = i & 4095;
    int s = r >> 9;
    int g = (r >> 5) & 15;
    int lane = r & 31;
    int o = g * 8 + (lane >> 2);
    int k0 = s * 8 + (lane & 3);
    float2 v;
    v.x = tf32r(wt[o * 576 + k0 * 9 + tap]);          // wt[o][ci][kh][kw], tap = kh*3+kw
    v.y = tf32r(wt[o * 576 + (k0 + 4) * 9 + tap]);
    ((float2*)g_Wf)[i] = v;
}

// ---------- main kernel: one CTA per (b, h-pair), 256 threads / 8 warps ----------
__global__ __launch_bounds__(256, 1)
void patchconv_mma(const float* __restrict__ x, const float* __restrict__ bias,
                   float* __restrict__ out) {
    extern __shared__ __align__(16) char smem[];
    float* sxs   = (float*)(smem + SM_XS);    // [r(4)][ci(64)][w(136)], w idx = xcol+4
    float* scs   = (float*)(smem + SM_CS);    // channel sums [r][w]
    float* sps   = (float*)(smem + SM_PS);    // 3x3 patch sums [hl][w]
    float* sbias = (float*)(smem + SM_BIAS);
    const uint32_t sb  = smem_u32(smem);
    const uint32_t mb0 = sb + SM_MB, mb1 = sb + SM_MB + 8;

    const int tid = threadIdx.x, lane = tid & 31, wid = tid >> 5;
    const int h0 = blockIdx.x * 2, b = blockIdx.y;

    if (tid == 0) { MB_INIT(mb0, 1); MB_INIT(mb1, 1); }
    if (tid < 128) sbias[tid] = bias[tid];
    __syncthreads();
    if (tid == 0) { MB_EXPECT(mb0, WBYTES); BULK_G2S(sb + SM_W, (const void*)g_Wf, WBYTES, mb0); }

    // ---- stage x: 4 halo rows, tf32-rounded, zero borders ----
    const float* xb = x + (size_t)b * CIN * HD * WD;
    for (int idx = wid; idx < 4 * 64; idx += 8) {
        int r = idx >> 6, ci = idx & 63;
        int hr = h0 - 1 + r;
        float4 v = make_float4(0.f, 0.f, 0.f, 0.f);
        if ((unsigned)hr < 128u)
            v = *(const float4*)(xb + ((size_t)ci * HD + hr) * WD + lane * 4);
        v.x = tf32r(v.x); v.y = tf32r(v.y); v.z = tf32r(v.z); v.w = tf32r(v.w);
        float* d = sxs + (r * 64 + ci) * XST;
        *(float4*)(d + 4 + lane * 4) = v;
        if (lane < 2) *(float4*)(d + lane * 132) = make_float4(0.f, 0.f, 0.f, 0.f);
    }
    __syncthreads();

    // ---- channel sums + 3x3 patch sums (rank-1 term) ----
    for (int p = tid; p < 4 * XST; p += 256) {
        int r = p / XST, w = p - r * XST;
        float s = 0.f;
        const float* c = sxs + r * 64 * XST + w;
        #pragma unroll 8
        for (int k = 0; k < 64; k++) s += c[k * XST];
        scs[p] = s;
    }
    __syncthreads();
    {
        int hl = tid >> 7, wo = tid & 127;
        float s = 0.f;
        #pragma unroll
        for (int kh = 0; kh < 3; kh++)
            #pragma unroll
            for (int kw = 0; kw < 3; kw++)
                s += scs[(hl + kh) * XST + wo + kw + 3];
        sps[tid] = s;
    }

    // ---- main loop: 9 taps, warp tile 64M x 64N ----
    const int warp_m = wid >> 1, warp_n = wid & 1;
    const int hl = warp_m >> 1;
    const int wb = (warp_m & 1) * 64;
    const int ob = warp_n * 64;

    float acc[4][8][4];
    #pragma unroll
    for (int mi = 0; mi < 4; mi++)
        #pragma unroll
        for (int ni = 0; ni < 8; ni++)
            #pragma unroll
            for (int j = 0; j < 4; j++) acc[mi][ni][j] = 0.f;

    #pragma unroll 1
    for (int t = 0; t < 9; t++) {
        const int buf = t & 1;
        if (t < 8 && tid == 0) {
            int nb = buf ^ 1;
            uint32_t m = nb ? mb1 : mb0;
            MB_EXPECT(m, WBYTES);
            BULK_G2S(sb + SM_W + nb * WBYTES, (const void*)(g_Wf + (t + 1) * 8192), WBYTES, m);
        }
        MB_WAIT(buf ? mb1 : mb0, (t >> 1) & 1);

        const int kh = t / 3, kw = t - kh * 3;
        const float* Ab = sxs + (hl + kh) * 64 * XST + (lane & 3) * XST + wb + kw + 3 + (lane >> 2);
        // B fragments: [s][g][lane][2]; this warp's g-window starts at warp_n*8
        const float2* Bb = (const float2*)(smem + SM_W + buf * WBYTES) + warp_n * 256 + lane;

        #pragma unroll
        for (int s = 0; s < 8; s++) {
            const float* Ap = Ab + s * 8 * XST;
            const float2* Bp = Bb + s * 512;
            float2 bq[8];
            #pragma unroll
            for (int ni = 0; ni < 8; ni++) bq[ni] = Bp[ni * 32];
            float a[4][4];
            #pragma unroll
            for (int mi = 0; mi < 4; mi++) {
                a[mi][0] = Ap[mi * 16];
                a[mi][1] = Ap[mi * 16 + 8];
                a[mi][2] = Ap[mi * 16 + 4 * XST];
                a[mi][3] = Ap[mi * 16 + 8 + 4 * XST];
            }
            #pragma unroll
            for (int mi = 0; mi < 4; mi++)
                #pragma unroll
                for (int ni = 0; ni < 8; ni++)
                    MMA8(acc[mi][ni], a[mi], bq[ni]);
        }
        __syncthreads();   // all warps done with buf before it is refilled at t+2
    }

    // ---- epilogue: + bias[o] + 0.1*(h+w)*patch_sum, 32B-sector-aligned stores ----
    const int hg = h0 + hl;
    float* outb = out + (size_t)b * OC * HD * WD + (size_t)hg * WD;
    #pragma unroll
    for (int mi = 0; mi < 4; mi++) {
        int w0r = wb + mi * 16 + (lane >> 2);
        float c0 = 0.1f * (float)(hg + w0r) * sps[hl * 128 + w0r];
        float c1 = 0.1f * (float)(hg + w0r + 8) * sps[hl * 128 + w0r + 8];
        #pragma unroll
        for (int ni = 0; ni < 8; ni++) {
            int o = ob + ni * 8 + (lane & 3) * 2;
            float bz0 = sbias[o], bz1 = sbias[o + 1];
            float* p0 = outb + (size_t)o * (HD * WD);
            float* p1 = p0 + HD * WD;
            p0[w0r]     = acc[mi][ni][0] + c0 + bz0;
            p1[w0r]     = acc[mi][ni][1] + c0 + bz1;
            p0[w0r + 8] = acc[mi][ni][2] + c1 + bz0;
            p1[w0r + 8] = acc[mi][ni][3] + c1 + bz1;
        }
    }
}

extern "C" void kernel_launch(void* const* d_in, const int* in_sizes, int n_in,
                              void* d_out, int out_size) {
    const float* x    = (const float*)d_in[0];
    const float* wt   = (const float*)d_in[1];
    const float* bias = (const float*)d_in[2];
    float* out        = (float*)d_out;
    cudaFuncSetAttribute(patchconv_mma, cudaFuncAttributeMaxDynamicSharedMemorySize, SM_TOT);
    prep_w<<<(9 * 8 * 16 * 32 + 255) / 256, 256>>>(wt);
    patchconv_mma<<<dim3(64, 16), 256, SM_TOT>>>(x, bias, out);
}

// round 7
// speedup vs baseline: 1.2025x; 1.0726x over previous
#include <cuda_runtime.h>
#include <cstdint>

#define HD 128
#define WD 128
#define OC 128
#define CIN 64
#define XST 136                 // x smem row stride (floats): conflict-free frag reads
#define WBYTES 32768            // one tap of pre-arranged B fragments

// smem byte offsets
#define SM_XS   0               // 4 * 64 * 136 * 4 = 139264
#define SM_W    139264          // 2 * 32768 = 65536
#define SM_CS   204800          // 4 * 136 * 4 = 2176
#define SM_PS   206976          // 2 * 128 * 4 = 1024
#define SM_BIAS 208000          // 512
#define SM_MB   208512          // wb0, wb1, cb0, cb1
#define SM_TOT  208560

// B fragments, register-image order: [tap][s(8)][g(16)][lane(32)][2]
__device__ __align__(128) float g_Wf[9 * 8 * 16 * 32 * 2];

// ---------- helpers ----------
__device__ __forceinline__ uint32_t smem_u32(const void* p) {
    uint32_t a;
    asm("{ .reg .u64 t; cvta.to.shared.u64 t, %1; cvt.u32.u64 %0, t; }" : "=r"(a) : "l"(p));
    return a;
}
__device__ __forceinline__ float tf32r(float v) {
    float r; asm("cvt.rna.tf32.f32 %0, %1;" : "=f"(r) : "f"(v)); return r;
}
#define MB_INIT(mb, c)   asm volatile("mbarrier.init.shared.b64 [%0], %1;" :: "r"(mb), "r"((uint32_t)(c)) : "memory")
#define MB_EXPECT(mb, n) asm volatile("mbarrier.arrive.expect_tx.shared.b64 _, [%0], %1;" :: "r"(mb), "r"((uint32_t)(n)) : "memory")
#define MB_ARRIVE(mb)    asm volatile("mbarrier.arrive.shared.b64 _, [%0];" :: "r"(mb) : "memory")
#define BULK_G2S(dst, src, n, mb) \
    asm volatile("cp.async.bulk.shared::cta.global.mbarrier::complete_tx::bytes [%0], [%1], %2, [%3];" \
                 :: "r"(dst), "l"(src), "r"((uint32_t)(n)), "r"(mb) : "memory")
#define MB_WAIT(mb, par) do {                                                          \
    uint32_t _m = (mb), _p = (par), _d;                                                \
    asm volatile("{\n\t.reg .pred p;\n\t"                                              \
        "mbarrier.try_wait.parity.acquire.cta.shared::cta.b64 p, [%1], %2;\n\t"        \
        "selp.b32 %0,1,0,p;\n\t}" : "=r"(_d) : "r"(_m), "r"(_p) : "memory");           \
    if (!_d) {                                                                         \
        asm volatile("{\n\t.reg .pred P1;\n\tWL_%=:\n\t"                               \
            "mbarrier.try_wait.parity.acquire.cta.shared::cta.b64 P1, [%0], %1, 0x989680;\n\t" \
            "@P1 bra.uni WDN_%=;\n\tbra.uni WL_%=;\n\tWDN_%=:\n\t}"                    \
            :: "r"(_m), "r"(_p) : "memory");                                           \
    }                                                                                  \
} while (0)

// m16n8k8 tf32 HMMA (sm_80+ baseline ISA)
#define MMA8(d, a, bq)                                                                 \
    asm volatile("mma.sync.aligned.m16n8k8.row.col.f32.tf32.tf32.f32 "                 \
        "{%0,%1,%2,%3}, {%4,%5,%6,%7}, {%8,%9}, {%0,%1,%2,%3};"                        \
        : "+f"((d)[0]), "+f"((d)[1]), "+f"((d)[2]), "+f"((d)[3])                       \
        : "r"(__float_as_uint((a)[0])), "r"(__float_as_uint((a)[1])),                  \
          "r"(__float_as_uint((a)[2])), "r"(__float_as_uint((a)[3])),                  \
          "r"(__float_as_uint((bq).x)), "r"(__float_as_uint((bq).y)))

// load frags for step ss (relative to bases) into slot sl
#define LOAD_FRAGS(sl, Abase, Bbase, ss) do {                                          \
    const float*  _Ap = (Abase) + (ss) * 8 * XST;                                      \
    const float2* _Bp = (Bbase) + (ss) * 512;                                          \
    _Pragma("unroll") for (int _ni = 0; _ni < 8; _ni++) bq[sl][_ni] = _Bp[_ni * 32];   \
    _Pragma("unroll") for (int _mi = 0; _mi < 4; _mi++) {                              \
        a[sl][_mi][0] = _Ap[_mi * 16];                                                 \
        a[sl][_mi][1] = _Ap[_mi * 16 + 8];                                             \
        a[sl][_mi][2] = _Ap[_mi * 16 + 4 * XST];                                       \
        a[sl][_mi][3] = _Ap[_mi * 16 + 8 + 4 * XST];                                   \
    }                                                                                  \
} while (0)

// ---------- prepass: weights -> per-thread B fragment images ----------
__global__ void prep_w(const float* __restrict__ wt) {
    int i = blockIdx.x * blockDim.x + threadIdx.x;   // one float2 per thread
    if (i >= 9 * 8 * 16 * 32) return;
    int tap = i >> 12;
    int r = i & 4095;
    int s = r >> 9;
    int g = (r >> 5) & 15;
    int lane = r & 31;
    int o = g * 8 + (lane >> 2);
    int k0 = s * 8 + (lane & 3);
    float2 v;
    v.x = tf32r(wt[o * 576 + k0 * 9 + tap]);          // wt[o][ci][kh][kw], tap = kh*3+kw
    v.y = tf32r(wt[o * 576 + (k0 + 4) * 9 + tap]);
    ((float2*)g_Wf)[i] = v;
}

// ---------- main kernel: one CTA per (b, h-pair), 256 threads / 8 warps ----------
__global__ __launch_bounds__(256, 1)
void patchconv_mma(const float* __restrict__ x, const float* __restrict__ bias,
                   float* __restrict__ out) {
    extern __shared__ __align__(16) char smem[];
    float* sxs   = (float*)(smem + SM_XS);    // [r(4)][ci(64)][w(136)], w idx = xcol+4
    float* scs   = (float*)(smem + SM_CS);    // channel sums [r][w]
    float* sps   = (float*)(smem + SM_PS);    // 3x3 patch sums [hl][w]
    float* sbias = (float*)(smem + SM_BIAS);
    const uint32_t sb  = smem_u32(smem);
    const uint32_t wb0 = sb + SM_MB,      wb1 = sb + SM_MB + 8;
    const uint32_t cb0 = sb + SM_MB + 16, cb1 = sb + SM_MB + 24;

    const int tid = threadIdx.x, lane = tid & 31, wid = tid >> 5;
    const int h0 = blockIdx.x * 2, b = blockIdx.y;

    if (tid == 0) { MB_INIT(wb0, 1); MB_INIT(wb1, 1); MB_INIT(cb0, 8); MB_INIT(cb1, 8); }
    if (tid < 128) sbias[tid] = bias[tid];
    __syncthreads();
    if (tid == 0) { MB_EXPECT(wb0, WBYTES); BULK_G2S(sb + SM_W, (const void*)g_Wf, WBYTES, wb0); }

    // ---- stage x: 4 halo rows, tf32-rounded, zero borders ----
    const float* xb = x + (size_t)b * CIN * HD * WD;
    for (int idx = wid; idx < 4 * 64; idx += 8) {
        int r = idx >> 6, ci = idx & 63;
        int hr = h0 - 1 + r;
        float4 v = make_float4(0.f, 0.f, 0.f, 0.f);
        if ((unsigned)hr < 128u)
            v = *(const float4*)(xb + ((size_t)ci * HD + hr) * WD + lane * 4);
        v.x = tf32r(v.x); v.y = tf32r(v.y); v.z = tf32r(v.z); v.w = tf32r(v.w);
        float* d = sxs + (r * 64 + ci) * XST;
        *(float4*)(d + 4 + lane * 4) = v;
        if (lane < 2) *(float4*)(d + lane * 132) = make_float4(0.f, 0.f, 0.f, 0.f);
    }
    __syncthreads();

    // ---- channel sums + 3x3 patch sums (rank-1 term) ----
    for (int p = tid; p < 4 * XST; p += 256) {
        int r = p / XST, w = p - r * XST;
        float s = 0.f;
        const float* c = sxs + r * 64 * XST + w;
        #pragma unroll 8
        for (int k = 0; k < 64; k++) s += c[k * XST];
        scs[p] = s;
    }
    __syncthreads();
    {
        int hl = tid >> 7, wo = tid & 127;
        float s = 0.f;
        #pragma unroll
        for (int kh = 0; kh < 3; kh++)
            #pragma unroll
            for (int kw = 0; kw < 3; kw++)
                s += scs[(hl + kh) * XST + wo + kw + 3];
        sps[tid] = s;
    }
    __syncthreads();

    // ---- main loop: 9 taps, warp tile 64M x 64N, no CTA barriers ----
    const int warp_m = wid >> 1, warp_n = wid & 1;
    const int hl = warp_m >> 1;
    const int wb = (warp_m & 1) * 64;
    const int ob = warp_n * 64;

    float acc[4][8][4];
    #pragma unroll
    for (int mi = 0; mi < 4; mi++)
        #pragma unroll
        for (int ni = 0; ni < 8; ni++)
            #pragma unroll
            for (int j = 0; j < 4; j++) acc[mi][ni][j] = 0.f;

    float a[2][4][4];
    float2 bq[2][8];

    // prologue: wait tap-0 weights, load step-0 frags into slot 0
    MB_WAIT(wb0, 0);
    {
        const float*  Ab = sxs + hl * 64 * XST + (lane & 3) * XST + wb + 3 + (lane >> 2);
        const float2* Bb = (const float2*)(smem + SM_W) + warp_n * 256 + lane;
        LOAD_FRAGS(0, Ab, Bb, 0);
    }

    #pragma unroll 1
    for (int t = 0; t < 9; t++) {
        const int buf = t & 1;
        // tid0: refill other buffer with tap t+1 weights once all warps consumed it
        if (t < 8 && tid == 0) {
            const uint32_t nbm = buf ? wb0 : wb1;
            const uint32_t ncb = buf ? cb0 : cb1;
            if (t >= 1) MB_WAIT(ncb, ((t - 1) >> 1) & 1);
            MB_EXPECT(nbm, WBYTES);
            BULK_G2S(sb + SM_W + (buf ^ 1) * WBYTES, (const void*)(g_Wf + (t + 1) * 8192), WBYTES, nbm);
        }

        const int kh = t / 3, kw = t - kh * 3;
        const float*  Ab = sxs + (hl + kh) * 64 * XST + (lane & 3) * XST + wb + kw + 3 + (lane >> 2);
        const float2* Bb = (const float2*)(smem + SM_W + buf * WBYTES) + warp_n * 256 + lane;

        #pragma unroll
        for (int s = 0; s < 8; s++) {
            const int cur = s & 1, nxt = cur ^ 1;
            if (s < 7) {
                LOAD_FRAGS(nxt, Ab, Bb, s + 1);
            } else {
                // all B-frag reads of tap t issued -> signal buffer consumed
                if (lane == 0) MB_ARRIVE(buf ? cb1 : cb0);
                if (t < 8) {
                    // prefetch tap t+1 step 0 (after its weights land)
                    MB_WAIT(buf ? wb0 : wb1, ((t + 1) >> 1) & 1);
                    const int nt = t + 1, nkh = nt / 3, nkw = nt - nkh * 3;
                    const float*  An = sxs + (hl + nkh) * 64 * XST + (lane & 3) * XST + wb + nkw + 3 + (lane >> 2);
                    const float2* Bn = (const float2*)(smem + SM_W + (nt & 1) * WBYTES) + warp_n * 256 + lane;
                    LOAD_FRAGS(nxt, An, Bn, 0);
                }
            }
            #pragma unroll
            for (int mi = 0; mi < 4; mi++)
                #pragma unroll
                for (int ni = 0; ni < 8; ni++)
                    MMA8(acc[mi][ni], a[cur][mi], bq[cur][ni]);
        }
    }

    // ---- epilogue: + bias[o] + 0.1*(h+w)*patch_sum, 32B-sector-aligned stores ----
    const int hg = h0 + hl;
    float* outb = out + (size_t)b * OC * HD * WD + (size_t)hg * WD;
    #pragma unroll
    for (int mi = 0; mi < 4; mi++) {
        int w0r = wb + mi * 16 + (lane >> 2);
        float c0 = 0.1f * (float)(hg + w0r) * sps[hl * 128 + w0r];
        float c1 = 0.1f * (float)(hg + w0r + 8) * sps[hl * 128 + w0r + 8];
        #pragma unroll
        for (int ni = 0; ni < 8; ni++) {
            int o = ob + ni * 8 + (lane & 3) * 2;
            float bz0 = sbias[o], bz1 = sbias[o + 1];
            float* p0 = outb + (size_t)o * (HD * WD);
            float* p1 = p0 + HD * WD;
            p0[w0r]     = acc[mi][ni][0] + c0 + bz0;
            p1[w0r]     = acc[mi][ni][1] + c0 + bz1;
            p0[w0r + 8] = acc[mi][ni][2] + c1 + bz0;
            p1[w0r + 8] = acc[mi][ni][3] + c1 + bz1;
        }
    }
}

extern "C" void kernel_launch(void* const* d_in, const int* in_sizes, int n_in,
                              void* d_out, int out_size) {
    const float* x    = (const float*)d_in[0];
    const float* wt   = (const float*)d_in[1];
    const float* bias = (const float*)d_in[2];
    float* out        = (float*)d_out;
    cudaFuncSetAttribute(patchconv_mma, cudaFuncAttributeMaxDynamicSharedMemorySize, SM_TOT);
    prep_w<<<(9 * 8 * 16 * 32 + 255) / 256, 256>>>(wt);
    patchconv_mma<<<dim3(64, 16), 256, SM_TOT>>>(x, bias, out);
}